// round 2
// baseline (speedup 1.0000x reference)
#include <cuda_runtime.h>
#include <cuda_bf16.h>
#include <cstdint>

#define N_NODES 100000
#define N_EDGES 1600000
#define IN_CH   256
#define HC      128        // HEADS*OUT_CH
#define NEG_SLOPE 0.2f

// ---------------- scratch (static device globals; no allocation) -------------
__device__ __align__(16) float g_feat[(size_t)N_NODES * HC];   // 51.2 MB
__device__ float g_esrc[N_NODES];
__device__ float g_etar[N_NODES];
__device__ float g_eself[N_NODES];
__device__ float g_esum[N_NODES];
__device__ int   g_counts[N_NODES];
__device__ int   g_offsets[N_NODES];
__device__ int   g_cursor[N_NODES];
__device__ int   g_srcs[N_EDGES];
__device__ float g_evals[N_EDGES];
__device__ int   g_is32;   // 1 if edge_index buffer holds int32, 0 if int64

// ---------------- Kernel 0: sniff edge_index dtype ---------------------------
// If the buffer is int32, interpreting it as int64 packs two indices per value,
// which lands outside [0, N_NODES) with overwhelming probability.
__global__ void k_detect(const long long* __restrict__ p) {
    if (blockIdx.x == 0 && threadIdx.x == 0) {
        int f = 0;
        for (int j = 0; j < 64; j++) {
            long long v = p[j];
            if (v < 0 || v >= (long long)N_NODES) f = 1;
        }
        g_is32 = f;
    }
}

__device__ __forceinline__ void load_edge(const void* ei, int i, int& t, int& s) {
    if (g_is32) {
        const int* p = (const int*)ei;
        t = p[i];
        s = p[N_EDGES + i];
    } else {
        const long long* p = (const long long*)ei;
        t = (int)p[i];
        s = (int)p[N_EDGES + i];
    }
}

// ---------------- Kernel 1: SGEMM feat = x @ W^T + b -------------------------
// Tile 128x128, BK=32, 256 threads, 8x8 microtile per thread.
__global__ __launch_bounds__(256) void k_gemm(const float* __restrict__ x,
                                              const float* __restrict__ W,
                                              const float* __restrict__ b) {
    __shared__ float xs[32][132];   // [k][row], padded
    __shared__ float ws[32][132];   // [k][col]

    const int tid = threadIdx.x;
    const int tx = tid & 15;        // 16 cols of threads
    const int ty = tid >> 4;        // 16 rows of threads
    const int row0 = blockIdx.x * 128;

    float acc[8][8];
#pragma unroll
    for (int i = 0; i < 8; i++)
#pragma unroll
        for (int j = 0; j < 8; j++) acc[i][j] = 0.f;

    for (int k0 = 0; k0 < IN_CH; k0 += 32) {
        // load x tile (128 rows x 32 k) transposed into xs[k][row]
#pragma unroll
        for (int l = 0; l < 4; l++) {
            int idx = tid + l * 256;        // 0..1023 float4 slots
            int r  = idx >> 3;              // row 0..127
            int kq = idx & 7;               // float4 index in k
            int grow = row0 + r;
            float4 v = make_float4(0.f, 0.f, 0.f, 0.f);
            if (grow < N_NODES)
                v = *reinterpret_cast<const float4*>(&x[(size_t)grow * IN_CH + k0 + kq * 4]);
            xs[kq * 4 + 0][r] = v.x;
            xs[kq * 4 + 1][r] = v.y;
            xs[kq * 4 + 2][r] = v.z;
            xs[kq * 4 + 3][r] = v.w;
        }
        // load W tile (128 cols x 32 k) transposed into ws[k][col]
#pragma unroll
        for (int l = 0; l < 4; l++) {
            int idx = tid + l * 256;
            int c  = idx >> 3;
            int kq = idx & 7;
            float4 v = *reinterpret_cast<const float4*>(&W[(size_t)c * IN_CH + k0 + kq * 4]);
            ws[kq * 4 + 0][c] = v.x;
            ws[kq * 4 + 1][c] = v.y;
            ws[kq * 4 + 2][c] = v.z;
            ws[kq * 4 + 3][c] = v.w;
        }
        __syncthreads();

#pragma unroll
        for (int kk = 0; kk < 32; kk++) {
            float a[8], bb[8];
            float4 a0 = *reinterpret_cast<const float4*>(&xs[kk][ty * 8]);
            float4 a1 = *reinterpret_cast<const float4*>(&xs[kk][ty * 8 + 4]);
            float4 b0 = *reinterpret_cast<const float4*>(&ws[kk][tx * 8]);
            float4 b1 = *reinterpret_cast<const float4*>(&ws[kk][tx * 8 + 4]);
            a[0]=a0.x; a[1]=a0.y; a[2]=a0.z; a[3]=a0.w;
            a[4]=a1.x; a[5]=a1.y; a[6]=a1.z; a[7]=a1.w;
            bb[0]=b0.x; bb[1]=b0.y; bb[2]=b0.z; bb[3]=b0.w;
            bb[4]=b1.x; bb[5]=b1.y; bb[6]=b1.z; bb[7]=b1.w;
#pragma unroll
            for (int i = 0; i < 8; i++)
#pragma unroll
                for (int j = 0; j < 8; j++)
                    acc[i][j] = fmaf(a[i], bb[j], acc[i][j]);
        }
        __syncthreads();
    }

    // epilogue: feat[row][col] = acc + b[col]
#pragma unroll
    for (int i = 0; i < 8; i++) {
        int grow = row0 + ty * 8 + i;
        if (grow >= N_NODES) break;
#pragma unroll
        for (int j = 0; j < 8; j += 4) {
            int col = tx * 8 + j;
            float4 bv = *reinterpret_cast<const float4*>(&b[col]);
            float4 o;
            o.x = acc[i][j + 0] + bv.x;
            o.y = acc[i][j + 1] + bv.y;
            o.z = acc[i][j + 2] + bv.z;
            o.w = acc[i][j + 3] + bv.w;
            *reinterpret_cast<float4*>(&g_feat[(size_t)grow * HC + col]) = o;
        }
    }
}

// ---------------- Kernel 2: per-node attention scalars + init ----------------
// One warp per node: e_src[n] = feat_row . att[:,0], e_tar[n] = feat_row . att[:,1]
__global__ __launch_bounds__(256) void k_epre(const float* __restrict__ att) {
    int warp = (blockIdx.x * blockDim.x + threadIdx.x) >> 5;
    if (warp >= N_NODES) return;
    int lane = threadIdx.x & 31;

    const float4* f4 = reinterpret_cast<const float4*>(g_feat);
    float4 f = f4[(size_t)warp * 32 + lane];
    // att is (128,2) row-major; channels lane*4 .. lane*4+3 -> att[8*lane .. 8*lane+7]
    float4 a0 = *reinterpret_cast<const float4*>(&att[lane * 8]);
    float4 a1 = *reinterpret_cast<const float4*>(&att[lane * 8 + 4]);

    float s0 = f.x * a0.x + f.y * a0.z + f.z * a1.x + f.w * a1.z;
    float s1 = f.x * a0.y + f.y * a0.w + f.z * a1.y + f.w * a1.w;
#pragma unroll
    for (int o = 16; o > 0; o >>= 1) {
        s0 += __shfl_xor_sync(0xffffffffu, s0, o);
        s1 += __shfl_xor_sync(0xffffffffu, s1, o);
    }
    if (lane == 0) {
        g_esrc[warp] = s0;
        g_etar[warp] = s1;
        float z = s0 + s1;
        float lz = z > 0.f ? z : NEG_SLOPE * z;
        float e = expf(lz);
        g_eself[warp] = e;
        g_esum[warp]  = e;
        g_counts[warp] = 0;
    }
}

// ---------------- Kernel 3: histogram of destination nodes -------------------
__global__ __launch_bounds__(256) void k_hist(const void* __restrict__ ei) {
    int i = blockIdx.x * blockDim.x + threadIdx.x;
    if (i >= N_EDGES) return;
    int t, s;
    load_edge(ei, i, t, s);
    if ((unsigned)t >= N_NODES || (unsigned)s >= N_NODES) return;  // safety guard
    atomicAdd(&g_counts[t], 1);
}

// ---------------- Kernel 4: exclusive prefix scan (single block) -------------
__global__ __launch_bounds__(1024) void k_scan() {
    __shared__ int warpsum[32];
    __shared__ int carry_s;
    if (threadIdx.x == 0) carry_s = 0;
    __syncthreads();
    int lane = threadIdx.x & 31, wid = threadIdx.x >> 5;
    for (int base = 0; base < N_NODES; base += 1024) {
        int i = base + threadIdx.x;
        int v = (i < N_NODES) ? g_counts[i] : 0;
        int xv = v;
#pragma unroll
        for (int o = 1; o < 32; o <<= 1) {
            int y = __shfl_up_sync(0xffffffffu, xv, o);
            if (lane >= o) xv += y;
        }
        if (lane == 31) warpsum[wid] = xv;
        __syncthreads();
        if (wid == 0) {
            int s = warpsum[lane];
#pragma unroll
            for (int o = 1; o < 32; o <<= 1) {
                int y = __shfl_up_sync(0xffffffffu, s, o);
                if (lane >= o) s += y;
            }
            warpsum[lane] = s;
        }
        __syncthreads();
        int incl = xv + (wid > 0 ? warpsum[wid - 1] : 0);
        int excl = incl - v;
        int c = carry_s;
        if (i < N_NODES) {
            g_offsets[i] = c + excl;
            g_cursor[i]  = c + excl;
        }
        int total = warpsum[31];
        __syncthreads();
        if (threadIdx.x == 0) carry_s = c + total;
        __syncthreads();
    }
}

// ---------------- Kernel 5: scatter edges into CSR, compute e, e_sum ---------
__global__ __launch_bounds__(256) void k_scatter(const void* __restrict__ ei) {
    int i = blockIdx.x * blockDim.x + threadIdx.x;
    if (i >= N_EDGES) return;
    int t, s;
    load_edge(ei, i, t, s);
    if ((unsigned)t >= N_NODES || (unsigned)s >= N_NODES) return;  // safety guard
    float z = g_esrc[s] + g_etar[t];
    float lz = z > 0.f ? z : NEG_SLOPE * z;
    float e = expf(lz);
    int pos = atomicAdd(&g_cursor[t], 1);
    g_srcs[pos]  = s;
    g_evals[pos] = e;
    atomicAdd(&g_esum[t], e);
}

// ---------------- Kernel 6: aggregation, one warp per node -------------------
__global__ __launch_bounds__(256) void k_agg(float* __restrict__ out) {
    int warp = (blockIdx.x * blockDim.x + threadIdx.x) >> 5;
    if (warp >= N_NODES) return;
    int lane = threadIdx.x & 31;

    const float4* f4 = reinterpret_cast<const float4*>(g_feat);
    int off = g_offsets[warp];
    int cnt = g_counts[warp];

    float4 acc = make_float4(0.f, 0.f, 0.f, 0.f);
    int j = 0;
#pragma unroll 1
    for (; j + 4 <= cnt; j += 4) {
#pragma unroll
        for (int u = 0; u < 4; u++) {
            int s = g_srcs[off + j + u];
            float e = g_evals[off + j + u];
            float4 f = f4[(size_t)s * 32 + lane];
            acc.x = fmaf(e, f.x, acc.x);
            acc.y = fmaf(e, f.y, acc.y);
            acc.z = fmaf(e, f.z, acc.z);
            acc.w = fmaf(e, f.w, acc.w);
        }
    }
    for (; j < cnt; j++) {
        int s = g_srcs[off + j];
        float e = g_evals[off + j];
        float4 f = f4[(size_t)s * 32 + lane];
        acc.x = fmaf(e, f.x, acc.x);
        acc.y = fmaf(e, f.y, acc.y);
        acc.z = fmaf(e, f.z, acc.z);
        acc.w = fmaf(e, f.w, acc.w);
    }

    float es  = g_eself[warp];
    float inv = 1.0f / g_esum[warp];
    float4 fs = f4[(size_t)warp * 32 + lane];
    float4 o;
    o.x = (acc.x + es * fs.x) * inv;
    o.y = (acc.y + es * fs.y) * inv;
    o.z = (acc.z + es * fs.z) * inv;
    o.w = (acc.w + es * fs.w) * inv;
    reinterpret_cast<float4*>(out)[(size_t)warp * 32 + lane] = o;
}

// ---------------- launch ------------------------------------------------------
extern "C" void kernel_launch(void* const* d_in, const int* in_sizes, int n_in,
                              void* d_out, int out_size) {
    // Bind inputs BY ELEMENT COUNT (robust to metadata ordering):
    //   x: 100000*256 = 25,600,000   edge_index: 2*1,600,000 = 3,200,000
    //   W: 128*256 = 32,768          b: 128                  att: 128*2 = 256
    const float* x   = nullptr;
    const void*  ei  = nullptr;
    const float* W   = nullptr;
    const float* b   = nullptr;
    const float* att = nullptr;
    for (int i = 0; i < n_in; i++) {
        switch (in_sizes[i]) {
            case 25600000: x   = (const float*)d_in[i]; break;
            case 3200000:  ei  = d_in[i];               break;
            case 32768:    W   = (const float*)d_in[i]; break;
            case 128:      b   = (const float*)d_in[i]; break;
            case 256:      att = (const float*)d_in[i]; break;
            default: break;
        }
    }
    float* out = (float*)d_out;
    (void)out_size;

    k_detect<<<1, 32>>>((const long long*)ei);

    int gemm_blocks = (N_NODES + 127) / 128;           // 782
    k_gemm<<<gemm_blocks, 256>>>(x, W, b);

    int node_warp_blocks = (N_NODES * 32 + 255) / 256; // 12500
    k_epre<<<node_warp_blocks, 256>>>(att);

    int edge_blocks = (N_EDGES + 255) / 256;           // 6250
    k_hist<<<edge_blocks, 256>>>(ei);

    k_scan<<<1, 1024>>>();

    k_scatter<<<edge_blocks, 256>>>(ei);

    k_agg<<<node_warp_blocks, 256>>>(out);
}